// round 1
// baseline (speedup 1.0000x reference)
#include <cuda_runtime.h>
#include <cuda_fp16.h>
#include <math.h>

#define BB 16
#define NN 2048

// 16 * 2048 * 2048 fp16 = 134 MB scratch (module-static; no runtime alloc)
static __device__ __half g_compat[(size_t)BB * NN * NN];
static __device__ float g_vbuf[2][BB * NN];

// ---------------------------------------------------------------------------
// v init: ones
// ---------------------------------------------------------------------------
__global__ void init_v_kernel() {
    int i = blockIdx.x * blockDim.x + threadIdx.x;
    if (i < BB * NN) g_vbuf[0][i] = 1.0f;
}

// ---------------------------------------------------------------------------
// Compat matrix build: compat[b][i][j] = max(1 - (|ai-aj| - |bi-bj|)^2/100, 0),
// zero diagonal. Stored fp16. One CTA = 16 rows of one batch.
// ---------------------------------------------------------------------------
__global__ __launch_bounds__(256) void compat_kernel(const float* __restrict__ src,
                                                     const float* __restrict__ tgt) {
    __shared__ float sx[NN], sy[NN], tx[NN], ty[NN];
    const int b = blockIdx.y;
    const int row0 = blockIdx.x * 16;
    const float2* s2p = (const float2*)(src + (size_t)b * NN * 2);
    const float2* t2p = (const float2*)(tgt + (size_t)b * NN * 2);
    for (int i = threadIdx.x; i < NN; i += 256) {
        float2 a = s2p[i]; sx[i] = a.x; sy[i] = a.y;
        float2 c = t2p[i]; tx[i] = c.x; ty[i] = c.y;
    }
    __syncthreads();
    const int warp = threadIdx.x >> 5, lane = threadIdx.x & 31;
    __half* base = g_compat + (size_t)b * NN * NN;
    for (int rr = warp; rr < 16; rr += 8) {
        const int i = row0 + rr;
        const float six = sx[i], siy = sy[i], tix = tx[i], tiy = ty[i];
        __half2* orow = (__half2*)(base + (size_t)i * NN);
        #pragma unroll 4
        for (int j2 = lane; j2 < NN / 2; j2 += 32) {
            const int j = j2 * 2;
            // element (i, j)
            float dx = six - sx[j], dy = siy - sy[j];
            float d2 = fmaf(dx, dx, dy * dy);
            float ds = d2 * rsqrtf(fmaxf(d2, 1e-20f));
            float ex = tix - tx[j], ey = tiy - ty[j];
            float e2 = fmaf(ex, ex, ey * ey);
            float dt = e2 * rsqrtf(fmaxf(e2, 1e-20f));
            float dd = ds - dt;
            float c0 = fmaxf(fmaf(dd * dd, -0.01f, 1.0f), 0.0f);
            if (j == i) c0 = 0.0f;
            // element (i, j+1)
            dx = six - sx[j + 1]; dy = siy - sy[j + 1];
            d2 = fmaf(dx, dx, dy * dy);
            ds = d2 * rsqrtf(fmaxf(d2, 1e-20f));
            ex = tix - tx[j + 1]; ey = tiy - ty[j + 1];
            e2 = fmaf(ex, ex, ey * ey);
            dt = e2 * rsqrtf(fmaxf(e2, 1e-20f));
            dd = ds - dt;
            float c1 = fmaxf(fmaf(dd * dd, -0.01f, 1.0f), 0.0f);
            if (j + 1 == i) c1 = 0.0f;
            orow[j2] = __floats2half2_rn(c0, c1);
        }
    }
}

// ---------------------------------------------------------------------------
// Power-iteration matvec: v_out = (M v_in) / 2048  (unnormalized power step;
// exact normalization deferred to solve kernel — scale-invariant).
// grid (32, 16): 64 rows per CTA, one row per warp, 8 rows sequentially.
// ---------------------------------------------------------------------------
__global__ __launch_bounds__(256) void matvec_kernel(int parity) {
    const float* __restrict__ vin = g_vbuf[parity];
    float* __restrict__ vout = g_vbuf[parity ^ 1];
    __shared__ float vv[NN];
    const int b = blockIdx.y;
    for (int i = threadIdx.x; i < NN; i += 256) vv[i] = vin[b * NN + i];
    __syncthreads();
    const int warp = threadIdx.x >> 5, lane = threadIdx.x & 31;
    const float2* vv2 = (const float2*)vv;
    const __half* base = g_compat + (size_t)b * NN * NN;
    #pragma unroll
    for (int rr = 0; rr < 8; rr++) {
        const int row = blockIdx.x * 64 + rr * 8 + warp;
        const int4* rp = (const int4*)(base + (size_t)row * NN);
        float acc = 0.f;
        #pragma unroll
        for (int s = 0; s < 8; s++) {
            const int k = s * 32 + lane;  // int4 index: 8 halves each
            int4 m = rp[k];
            __half2 h0 = *(__half2*)&m.x;
            __half2 h1 = *(__half2*)&m.y;
            __half2 h2 = *(__half2*)&m.z;
            __half2 h3 = *(__half2*)&m.w;
            float2 f0 = __half22float2(h0);
            float2 f1 = __half22float2(h1);
            float2 f2 = __half22float2(h2);
            float2 f3 = __half22float2(h3);
            float2 va = vv2[k * 4 + 0], vb = vv2[k * 4 + 1];
            float2 vc = vv2[k * 4 + 2], vd = vv2[k * 4 + 3];
            acc = fmaf(f0.x, va.x, acc); acc = fmaf(f0.y, va.y, acc);
            acc = fmaf(f1.x, vb.x, acc); acc = fmaf(f1.y, vb.y, acc);
            acc = fmaf(f2.x, vc.x, acc); acc = fmaf(f2.y, vc.y, acc);
            acc = fmaf(f3.x, vd.x, acc); acc = fmaf(f3.y, vd.y, acc);
        }
        #pragma unroll
        for (int off = 16; off; off >>= 1)
            acc += __shfl_down_sync(0xffffffffu, acc, off);
        if (lane == 0) vout[b * NN + row] = acc * (1.0f / 2048.0f);
    }
}

// ---------------------------------------------------------------------------
// Solve: per batch — normalize v, build w, initial Kabsch fit (closed-form 2x2
// SVD), 5 IRLS refinement rounds, write transformed src points.
// ---------------------------------------------------------------------------
__device__ __forceinline__ void reduceK(float* vals, int K, float* scratch) {
    const int tid = threadIdx.x, lane = tid & 31, w = tid >> 5;
    for (int k = 0; k < K; k++) {
        float v = vals[k];
        #pragma unroll
        for (int off = 16; off; off >>= 1)
            v += __shfl_down_sync(0xffffffffu, v, off);
        if (lane == 0) scratch[w * 9 + k] = v;
    }
    __syncthreads();
    if (tid == 0) {
        for (int k = 0; k < K; k++) {
            float s = 0.f;
            for (int ww = 0; ww < 8; ww++) s += scratch[ww * 9 + k];
            vals[k] = s;
        }
    }
}

__global__ __launch_bounds__(256) void solve_kernel(const float* __restrict__ src,
                                                    const float* __restrict__ tgt,
                                                    float* __restrict__ out) {
    __shared__ float sax[NN], say[NN], sbx[NN], sby[NN];
    __shared__ float scratch[8 * 9];
    __shared__ float sRT[4];  // c, s, tx, ty
    __shared__ float sWinv;
    const int b = blockIdx.x;
    const int tid = threadIdx.x;
    const float2* s2p = (const float2*)(src + (size_t)b * NN * 2);
    const float2* t2p = (const float2*)(tgt + (size_t)b * NN * 2);
    for (int i = tid; i < NN; i += 256) {
        float2 a = s2p[i]; sax[i] = a.x; say[i] = a.y;
        float2 c = t2p[i]; sbx[i] = c.x; sby[i] = c.y;
    }

    // w = v_hat / (sum(v_hat) + 1e-6),  v_hat = v / ||v||
    //   => w_n = v_n / (sum(v) + 1e-6 * ||v||)
    float vloc[8];
    float vals[9];
    float p_s2 = 0.f, p_sv = 0.f;
    #pragma unroll
    for (int p = 0; p < 8; p++) {
        float v = g_vbuf[0][b * NN + tid + 256 * p];
        vloc[p] = v;
        p_s2 = fmaf(v, v, p_s2);
        p_sv += v;
    }
    vals[0] = p_s2; vals[1] = p_sv;
    __syncthreads();  // point arrays ready; scratch safe
    reduceK(vals, 2, scratch);
    if (tid == 0) {
        float nrm = sqrtf(vals[0]);
        sWinv = 1.0f / (vals[1] + 1e-6f * nrm);
    }
    __syncthreads();
    const float winv = sWinv;

    float cth = 1.f, sth = 0.f, ttx = 0.f, tty = 0.f;
    for (int round = 0; round < 6; round++) {
        #pragma unroll
        for (int k = 0; k < 9; k++) vals[k] = 0.f;
        #pragma unroll
        for (int p = 0; p < 8; p++) {
            const int n = tid + 256 * p;
            const float ax = sax[n], ay = say[n], bx = sbx[n], by = sby[n];
            float w;
            if (round == 0) {
                w = vloc[p] * winv;
            } else {
                float px = fmaf(cth, ax, fmaf(-sth, ay, ttx));
                float py = fmaf(sth, ax, fmaf(cth, ay, tty));
                float ex = px - bx, ey = py - by;
                float L2 = sqrtf(fmaf(ex, ex, ey * ey));
                float q = L2 * 0.25f;
                w = (L2 < 4.0f) ? 1.0f / fmaf(q, q, 1.0f) : 0.0f;
            }
            vals[0] += w;
            vals[1] = fmaf(w, ax, vals[1]);
            vals[2] = fmaf(w, ay, vals[2]);
            vals[3] = fmaf(w, bx, vals[3]);
            vals[4] = fmaf(w, by, vals[4]);
            vals[5] = fmaf(w * ax, bx, vals[5]);
            vals[6] = fmaf(w * ax, by, vals[6]);
            vals[7] = fmaf(w * ay, bx, vals[7]);
            vals[8] = fmaf(w * ay, by, vals[8]);
        }
        __syncthreads();  // everyone done reading sRT/scratch from last round
        reduceK(vals, 9, scratch);
        if (tid == 0) {
            const float W = vals[0];
            const float ws = W + 1e-6f;
            const float cAx = vals[1] / ws, cAy = vals[2] / ws;
            const float cBx = vals[3] / ws, cBy = vals[4] / ws;
            // H = sum w (A-cA)(B-cB)^T expanded exactly
            const float H00 = vals[5] - cAx * vals[3] - vals[1] * cBx + W * cAx * cBx;
            const float H01 = vals[6] - cAx * vals[4] - vals[1] * cBy + W * cAx * cBy;
            const float H10 = vals[7] - cAy * vals[3] - vals[2] * cBx + W * cAy * cBx;
            const float H11 = vals[8] - cAy * vals[4] - vals[2] * cBy + W * cAy * cBy;
            // closed-form 2x2 Kabsch (== V diag(1,det) U^T from SVD)
            const float aa = H00 + H11, bb = H01 - H10;
            const float r = sqrtf(fmaf(aa, aa, bb * bb)) + 1e-30f;
            const float c = aa / r, s = bb / r;
            sRT[0] = c; sRT[1] = s;
            sRT[2] = cBx - (c * cAx - s * cAy);
            sRT[3] = cBy - (s * cAx + c * cAy);
        }
        __syncthreads();
        cth = sRT[0]; sth = sRT[1]; ttx = sRT[2]; tty = sRT[3];
    }

    float2* outp = (float2*)(out + (size_t)b * NN * 2);
    #pragma unroll
    for (int p = 0; p < 8; p++) {
        const int n = tid + 256 * p;
        const float ax = sax[n], ay = say[n];
        float2 o;
        o.x = fmaf(cth, ax, fmaf(-sth, ay, ttx));
        o.y = fmaf(sth, ax, fmaf(cth, ay, tty));
        outp[n] = o;
    }
}

// ---------------------------------------------------------------------------
extern "C" void kernel_launch(void* const* d_in, const int* in_sizes, int n_in,
                              void* d_out, int out_size) {
    const float* src = (const float*)d_in[0];
    const float* tgt = (const float*)d_in[1];
    float* out = (float*)d_out;

    init_v_kernel<<<(BB * NN + 255) / 256, 256>>>();
    compat_kernel<<<dim3(128, BB), 256>>>(src, tgt);
    for (int it = 0; it < 10; it++)
        matvec_kernel<<<dim3(32, BB), 256>>>(it & 1);
    solve_kernel<<<BB, 256>>>(src, tgt, out);
}